// round 10
// baseline (speedup 1.0000x reference)
#include <cuda_runtime.h>
#include <math.h>

#define G     1024
#define GM    (G - 1)
#define NA    262144
#define NC    8
#define DT_F  0.1f
#define DEC_F 0.99f
#define SANG  0.6f
#define SLEN  3.0f

// Scratch (static device globals; no allocation anywhere)
__device__ float g_tmp1[NC * G * G];      // horizontal 3-sum, (C,G,G)       32 MB
__device__ float g_box[G * G * NC];       // 3x3 box sum, transposed (G,G,C) 32 MB
__device__ float g_dpher[NA * NC];        // per-agent pheromone delta        8 MB
__device__ int   g_winner[G * G];         // last-writer agent index + 1      4 MB (zero-init)

typedef unsigned long long u64;
__device__ __forceinline__ u64 pack2(float a, float b) {
    u64 r; asm("mov.b64 %0, {%1, %2};" : "=l"(r) : "f"(a), "f"(b)); return r;
}
__device__ __forceinline__ void unpack2(u64 v, float& a, float& b) {
    asm("mov.b64 {%0, %1}, %2;" : "=f"(a), "=f"(b) : "l"(v));
}
__device__ __forceinline__ void fma2(u64& d, u64 a, u64 b) {
    asm("fma.rn.f32x2 %0, %1, %2, %0;" : "+l"(d) : "l"(a), "l"(b));
}
__device__ __forceinline__ float tanh_ap(float x) {
    float y; asm("tanh.approx.f32 %0, %1;" : "=f"(y) : "f"(x)); return y;
}

// ---------------------------------------------------------------------------
// Pass 1a: horizontal wrapped 3-sum along y. (R2 verbatim — proven fastest)
// ---------------------------------------------------------------------------
__global__ void k_hsum(const float* __restrict__ lat) {
    int t   = blockIdx.x * blockDim.x + threadIdx.x;   // C*G*G/4 threads
    int y0  = (t & 255) << 2;
    int row = t >> 8;                                  // c*G + x
    const float* r = lat + (size_t)row * G;
    float4 m = *(const float4*)(r + y0);
    float lm = __ldg(r + ((y0 + GM) & GM));
    float rp = __ldg(r + ((y0 + 4) & GM));
    float4 o;
    o.x = lm  + m.x + m.y;
    o.y = m.x + m.y + m.z;
    o.z = m.y + m.z + m.w;
    o.w = m.z + m.w + rp;
    *(float4*)(g_tmp1 + (size_t)row * G + y0) = o;
}

// ---------------------------------------------------------------------------
// Pass 1b: vertical wrapped 3-sum along x + transpose to (x,y,c).
// ---------------------------------------------------------------------------
__global__ void k_vsum() {
    int t  = blockIdx.x * blockDim.x + threadIdx.x;    // G*G threads
    int y  = t & GM;
    int x  = t >> 10;
    int xm = (x + GM) & GM;
    int xp = (x + 1) & GM;
    float o[NC];
#pragma unroll
    for (int c = 0; c < NC; c++) {
        const float* p = g_tmp1 + (size_t)c * (G * G);
        o[c] = p[xm * G + y] + p[x * G + y] + p[xp * G + y];
    }
    float4* dst = (float4*)(g_box + (size_t)t * NC);
    dst[0] = make_float4(o[0], o[1], o[2], o[3]);
    dst[1] = make_float4(o[4], o[5], o[6], o[7]);
}

// ---------------------------------------------------------------------------
// Pass 2: 2 agents/thread, agents packed into f32x2 lanes. Weights stored
// DUPLICATED in smem (float2 {w,w}) so packed b-operands come from LDS.128.
// ---------------------------------------------------------------------------
__device__ __forceinline__ void sense24(float px, float py, float vx, float vy,
                                        float* __restrict__ x) {
    const float CA = 0.8253356149096783f;   // cos(0.6)
    const float SA = 0.5646424733950354f;   // sin(0.6)
    float rinv = rsqrtf(vx * vx + vy * vy);
    float c0 = vx * rinv, s0 = vy * rinv;
    float cd[3], sd[3];
    cd[0] = c0;                 sd[0] = s0;
    cd[1] = c0 * CA - s0 * SA;  sd[1] = s0 * CA + c0 * SA;
    cd[2] = c0 * CA + s0 * SA;  sd[2] = s0 * CA - c0 * SA;
#pragma unroll
    for (int s = 0; s < 3; s++) {
        int ix = ((int)rintf(px + SLEN * cd[s])) & GM;
        int iy = ((int)rintf(py + SLEN * sd[s])) & GM;
        const float4* bp = (const float4*)(g_box + ((size_t)(ix * G + iy)) * NC);
        float4 u = bp[0], v = bp[1];
        x[s * 8 + 0] = u.x; x[s * 8 + 1] = u.y; x[s * 8 + 2] = u.z; x[s * 8 + 3] = u.w;
        x[s * 8 + 4] = v.x; x[s * 8 + 5] = v.y; x[s * 8 + 6] = v.z; x[s * 8 + 7] = v.w;
    }
}

#define W2ROW 24   // layer-2 dup row: 10 weights x2 = 20 floats, padded to 24

__global__ __launch_bounds__(256) void k_agent(
    const float* __restrict__ pos, const float* __restrict__ vel,
    const float* __restrict__ W1,  const float* __restrict__ b1,
    const float* __restrict__ W2,  const float* __restrict__ b2,
    float* __restrict__ out)
{
    __shared__ __align__(16) float sW1d[24 * 64 * 2];   // {w,w} pairs, 12 KB
    __shared__ __align__(16) float sB1d[64 * 2];
    __shared__ __align__(16) float sW2d[64 * W2ROW];    // 6 KB
    __shared__ __align__(16) float sB2d[24];

    int tid = threadIdx.x;
    for (int i = tid; i < 24 * 64; i += 256) {
        float w = __ldg(W1 + i);
        ((float2*)sW1d)[i] = make_float2(w, w);
    }
    if (tid < 64) {
        float b = __ldg(b1 + tid);
        ((float2*)sB1d)[tid] = make_float2(b, b);
    }
    for (int i = tid; i < 64 * (W2ROW / 2); i += 256) {
        int k = i / (W2ROW / 2), m = i - k * (W2ROW / 2);
        float w = (m < 10) ? __ldg(W2 + k * 10 + m) : 0.0f;
        ((float2*)sW2d)[k * (W2ROW / 2) + m] = make_float2(w, w);
    }
    if (tid < 12) {
        float b = (tid < 10) ? __ldg(b2 + tid) : 0.0f;
        ((float2*)sB2d)[tid] = make_float2(b, b);
    }
    __syncthreads();

    int aA = blockIdx.x * 512 + tid;     // two agents per thread
    int aB = aA + 256;

    float pxA = pos[aA], pyA = pos[NA + aA];
    float vxA = vel[aA], vyA = vel[NA + aA];
    float pxB = pos[aB], pyB = pos[NA + aB];
    float vxB = vel[aB], vyB = vel[NA + aB];

    float xA[24], xB[24];
    sense24(pxA, pyA, vxA, vyA, xA);
    sense24(pxB, pyB, vxB, vyB, xB);

    u64 xk[24];                           // lanes = (agent A, agent B)
#pragma unroll
    for (int k = 0; k < 24; k++) xk[k] = pack2(xA[k], xB[k]);

    u64 oc[10];
    {
        const ulonglong2* bq = (const ulonglong2*)sB2d;
        ulonglong2 q0 = bq[0], q1 = bq[1], q2 = bq[2], q3 = bq[3], q4 = bq[4];
        oc[0] = q0.x; oc[1] = q0.y; oc[2] = q1.x; oc[3] = q1.y;
        oc[4] = q2.x; oc[5] = q2.y; oc[6] = q3.x; oc[7] = q3.y;
        oc[8] = q4.x; oc[9] = q4.y;
    }

#pragma unroll
    for (int jq = 0; jq < 16; jq++) {
        const ulonglong2* bb = (const ulonglong2*)&sB1d[jq * 8];
        ulonglong2 b01 = bb[0], b23 = bb[1];
        u64 ac0 = b01.x, ac1 = b01.y, ac2 = b23.x, ac3 = b23.y;
#pragma unroll
        for (int k = 0; k < 24; k++) {
            const ulonglong2* wr = (const ulonglong2*)&sW1d[(k * 64 + jq * 4) * 2];
            ulonglong2 wA = wr[0], wB = wr[1];
            u64 xv = xk[k];
            fma2(ac0, xv, wA.x);
            fma2(ac1, xv, wA.y);
            fma2(ac2, xv, wB.x);
            fma2(ac3, xv, wB.y);
        }
        u64 hp[4];
        {
            float a0, b0; unpack2(ac0, a0, b0); hp[0] = pack2(tanh_ap(a0), tanh_ap(b0));
            float a1, b1v; unpack2(ac1, a1, b1v); hp[1] = pack2(tanh_ap(a1), tanh_ap(b1v));
            float a2, b2v; unpack2(ac2, a2, b2v); hp[2] = pack2(tanh_ap(a2), tanh_ap(b2v));
            float a3, b3v; unpack2(ac3, a3, b3v); hp[3] = pack2(tanh_ap(a3), tanh_ap(b3v));
        }
#pragma unroll
        for (int u = 0; u < 4; u++) {
            int j = jq * 4 + u;
            const ulonglong2* wr = (const ulonglong2*)&sW2d[j * W2ROW];
            ulonglong2 w0 = wr[0], w1 = wr[1], w2 = wr[2], w3 = wr[3], w4 = wr[4];
            u64 hu = hp[u];
            fma2(oc[0], hu, w0.x); fma2(oc[1], hu, w0.y);
            fma2(oc[2], hu, w1.x); fma2(oc[3], hu, w1.y);
            fma2(oc[4], hu, w2.x); fma2(oc[5], hu, w2.y);
            fma2(oc[6], hu, w3.x); fma2(oc[7], hu, w3.y);
            fma2(oc[8], hu, w4.x); fma2(oc[9], hu, w4.y);
        }
    }

    float ov[10][2];
#pragma unroll
    for (int m = 0; m < 10; m++) unpack2(oc[m], ov[m][0], ov[m][1]);

    {
        float npx = pxA + ov[0][0] * DT_F, npy = pyA + ov[1][0] * DT_F;
        npx -= floorf(npx * (1.0f / G)) * (float)G;
        npy -= floorf(npy * (1.0f / G)) * (float)G;
        out[aA] = npx; out[NA + aA] = npy;
        out[2 * NA + aA] = ov[0][0]; out[3 * NA + aA] = ov[1][0];
        float4* dp = (float4*)(g_dpher + (size_t)aA * NC);
        dp[0] = make_float4(ov[2][0], ov[3][0], ov[4][0], ov[5][0]);
        dp[1] = make_float4(ov[6][0], ov[7][0], ov[8][0], ov[9][0]);
        int pix = (int)rintf(pxA) & GM, piy = (int)rintf(pyA) & GM;
        atomicMax(&g_winner[pix * G + piy], aA + 1);
    }
    {
        float npx = pxB + ov[0][1] * DT_F, npy = pyB + ov[1][1] * DT_F;
        npx -= floorf(npx * (1.0f / G)) * (float)G;
        npy -= floorf(npy * (1.0f / G)) * (float)G;
        out[aB] = npx; out[NA + aB] = npy;
        out[2 * NA + aB] = ov[0][1]; out[3 * NA + aB] = ov[1][1];
        float4* dp = (float4*)(g_dpher + (size_t)aB * NC);
        dp[0] = make_float4(ov[2][1], ov[3][1], ov[4][1], ov[5][1]);
        dp[1] = make_float4(ov[6][1], ov[7][1], ov[8][1], ov[9][1]);
        int pix = (int)rintf(pxB) & GM, piy = (int)rintf(pyB) & GM;
        atomicMax(&g_winner[pix * G + piy], aB + 1);
    }
}

// ---------------------------------------------------------------------------
// Pass 3: resolve deposits + decay; 4 cells x 8 channels per thread (float4).
// (R6 verbatim) Resets g_winner so graph replays are identical.
// ---------------------------------------------------------------------------
__global__ void k_update(const float* __restrict__ lat, float* __restrict__ out) {
    int t = blockIdx.x * blockDim.x + threadIdx.x;     // G*G/4 threads
    int4 w4 = ((const int4*)g_winner)[t];
    int wl[4] = {w4.x, w4.y, w4.z, w4.w};
    if (wl[0] | wl[1] | wl[2] | wl[3])
        ((int4*)g_winner)[t] = make_int4(0, 0, 0, 0);

    float dp[4][NC];
#pragma unroll
    for (int u = 0; u < 4; u++) {
        if (wl[u]) {
            const float4* q = (const float4*)(g_dpher + (size_t)(wl[u] - 1) * NC);
            float4 a = q[0], b = q[1];
            dp[u][0] = a.x; dp[u][1] = a.y; dp[u][2] = a.z; dp[u][3] = a.w;
            dp[u][4] = b.x; dp[u][5] = b.y; dp[u][6] = b.z; dp[u][7] = b.w;
        }
    }

    const float4* l4 = (const float4*)lat;
    float4*       o4 = (float4*)(out + 4 * NA);
#pragma unroll
    for (int c = 0; c < NC; c++) {
        float4 v = l4[(size_t)c * (G * G / 4) + t];
        float* vv = (float*)&v;
#pragma unroll
        for (int u = 0; u < 4; u++)
            if (wl[u]) vv[u] = fmaxf(vv[u] + DT_F * dp[u][c], 0.0f);
        v.x *= DEC_F; v.y *= DEC_F; v.z *= DEC_F; v.w *= DEC_F;
        o4[(size_t)c * (G * G / 4) + t] = v;
    }
}

// ---------------------------------------------------------------------------
extern "C" void kernel_launch(void* const* d_in, const int* in_sizes, int n_in,
                              void* d_out, int out_size) {
    const float* pos = (const float*)d_in[0];
    const float* vel = (const float*)d_in[1];
    const float* lat = (const float*)d_in[2];
    const float* W1  = (const float*)d_in[3];
    const float* b1  = (const float*)d_in[4];
    const float* W2  = (const float*)d_in[5];
    const float* b2  = (const float*)d_in[6];
    float* out = (float*)d_out;

    k_hsum  <<<(NC * G * G / 4) / 256, 256>>>(lat);
    k_vsum  <<<(G * G) / 256, 256>>>();
    k_agent <<<NA / 512, 256>>>(pos, vel, W1, b1, W2, b2, out);
    k_update<<<(G * G / 4) / 256, 256>>>(lat, out);
}